// round 2
// baseline (speedup 1.0000x reference)
#include <cuda_runtime.h>
#include <cstdint>

#define NN 4096
#define DD 1024
#define BM 128
#define BN 128
#define BK 16

// Per-row argmin keys: (orderable(value) << 32) | col_index.  min key == argmin
// with first-index tie-break, identical to jnp.argmin semantics.
__device__ unsigned long long g_ap[NN];
__device__ unsigned long long g_an[NN];
__device__ int g_lab[NN];
__device__ int g_is64;

// ---------------------------------------------------------------------------
// Detect whether the labels buffer is int64 or int32 (JAX silently demotes
// int64 -> int32 when x64 is disabled).  View the first 4096 int32 words
// (always in-bounds for either dtype).  If the buffer is int64 (little-endian),
// every odd word is a high word == 0.  If int32, odd words are random labels
// in [0,64) — all-zero has probability ~64^-2048.
// ---------------------------------------------------------------------------
__global__ void detect_kernel(const int* __restrict__ lab32) {
    __shared__ int any;
    if (threadIdx.x == 0) any = 0;
    __syncthreads();
    int acc = 0;
    for (int i = 1 + 2 * threadIdx.x; i < 4096; i += 2 * blockDim.x)
        acc |= lab32[i];
    if (acc) atomicOr(&any, 1);
    __syncthreads();
    if (threadIdx.x == 0) g_is64 = (any == 0) ? 1 : 0;
}

__global__ void init_kernel(const int* __restrict__ lab32) {
    int i = blockIdx.x * blockDim.x + threadIdx.x;
    if (i < NN) {
        g_ap[i] = 0xFFFFFFFFFFFFFFFFull;
        g_an[i] = 0xFFFFFFFFFFFFFFFFull;
        g_lab[i] = g_is64 ? lab32[2 * i] : lab32[i];
    }
}

__device__ __forceinline__ unsigned float_order(float f) {
    unsigned u = __float_as_uint(f);
    return (u & 0x80000000u) ? ~u : (u | 0x80000000u);
}

// ---------------------------------------------------------------------------
// Fused SGEMM (S = X X^T tile) + masked argmin epilogue.
// Block: 128x128 output tile, 256 threads, 8x8 per-thread micro-tile.
// ---------------------------------------------------------------------------
__global__ __launch_bounds__(256)
void gemm_argmin(const float* __restrict__ X) {
    __shared__ float As[BK][BM + 4];
    __shared__ float Bs[BK][BN + 4];
    __shared__ int labA[BM];
    __shared__ int labB[BN];

    const int t  = threadIdx.x;
    const int tx = t & 15;        // 0..15 -> column group
    const int ty = t >> 4;        // 0..15 -> row group
    const int rowBase = blockIdx.y * BM;
    const int colBase = blockIdx.x * BN;

    if (t < BM)       labA[t]       = g_lab[rowBase + t];
    else              labB[t - BM]  = g_lab[colBase + (t - BM)];

    float acc[8][8];
#pragma unroll
    for (int i = 0; i < 8; i++)
#pragma unroll
        for (int j = 0; j < 8; j++) acc[i][j] = 0.0f;

    const float* Arow = X + (size_t)rowBase * DD;
    const float* Brow = X + (size_t)colBase * DD;

    const int lr  = t >> 2;   // 0..63  (row within half-tile)
    const int lc4 = t & 3;    // 0..3   (float4 column)

    for (int k0 = 0; k0 < DD; k0 += BK) {
#pragma unroll
        for (int h = 0; h < 2; h++) {
            const int r = lr + h * 64;
            float4 va = *(const float4*)(Arow + (size_t)r * DD + k0 + lc4 * 4);
            As[lc4 * 4 + 0][r] = va.x;
            As[lc4 * 4 + 1][r] = va.y;
            As[lc4 * 4 + 2][r] = va.z;
            As[lc4 * 4 + 3][r] = va.w;
            float4 vb = *(const float4*)(Brow + (size_t)r * DD + k0 + lc4 * 4);
            Bs[lc4 * 4 + 0][r] = vb.x;
            Bs[lc4 * 4 + 1][r] = vb.y;
            Bs[lc4 * 4 + 2][r] = vb.z;
            Bs[lc4 * 4 + 3][r] = vb.w;
        }
        __syncthreads();

#pragma unroll
        for (int kk = 0; kk < BK; kk++) {
            float a[8], b[8];
#pragma unroll
            for (int i = 0; i < 8; i++) a[i] = As[kk][ty * 8 + i];
#pragma unroll
            for (int j = 0; j < 8; j++) b[j] = Bs[kk][tx * 8 + j];
#pragma unroll
            for (int i = 0; i < 8; i++)
#pragma unroll
                for (int j = 0; j < 8; j++)
                    acc[i][j] += a[i] * b[j];
        }
        __syncthreads();
    }

    // ---- masked argmin epilogue -------------------------------------------
#pragma unroll
    for (int i = 0; i < 8; i++) {
        const int r   = rowBase + ty * 8 + i;
        const int lri = labA[ty * 8 + i];
        unsigned long long kap = 0xFFFFFFFFFFFFFFFFull;
        unsigned long long kan = 0xFFFFFFFFFFFFFFFFull;
#pragma unroll
        for (int j = 0; j < 8; j++) {
            const int c   = colBase + tx * 8 + j;
            const bool same = (lri == labB[tx * 8 + j]);
            const float v = acc[i][j];
            // d_ap: +2 unless (same label AND not self); d_an: +2 unless diff label
            const float vap = v + ((same && (r != c)) ? 0.0f : 2.0f);
            const float van = v + (same ? 2.0f : 0.0f);
            unsigned long long k1 =
                ((unsigned long long)float_order(vap) << 32) | (unsigned)c;
            unsigned long long k2 =
                ((unsigned long long)float_order(van) << 32) | (unsigned)c;
            kap = (k1 < kap) ? k1 : kap;
            kan = (k2 < kan) ? k2 : kan;
        }
        // reduce across the 16 lanes (tx) holding this row
#pragma unroll
        for (int off = 8; off >= 1; off >>= 1) {
            unsigned long long o1 = __shfl_xor_sync(0xffffffffu, kap, off);
            unsigned long long o2 = __shfl_xor_sync(0xffffffffu, kan, off);
            kap = (o1 < kap) ? o1 : kap;
            kan = (o2 < kan) ? o2 : kan;
        }
        if (tx == 0) {
            atomicMin(&g_ap[r], kap);
            atomicMin(&g_an[r], kan);
        }
    }
}

// ---------------------------------------------------------------------------
// Gather: out[0][r][:] = X[id_ap[r]], out[1][r][:] = X[id_an[r]]
// ---------------------------------------------------------------------------
__global__ void gather_kernel(const float* __restrict__ X, float* __restrict__ out) {
    const int r     = blockIdx.x;
    const int which = blockIdx.y;
    const unsigned idx =
        (unsigned)((which ? g_an[r] : g_ap[r]) & 0xFFFFFFFFull);
    const float4* src = (const float4*)(X + (size_t)idx * DD);
    float4* dst = (float4*)(out + ((size_t)which * NN + r) * DD);
    for (int i = threadIdx.x; i < DD / 4; i += blockDim.x)
        dst[i] = src[i];
}

extern "C" void kernel_launch(void* const* d_in, const int* in_sizes, int n_in,
                              void* d_out, int out_size) {
    const float* X   = (const float*)d_in[0];
    const int*   lab = (const int*)d_in[1];
    float*       out = (float*)d_out;

    detect_kernel<<<1, 256>>>(lab);
    init_kernel<<<16, 256>>>(lab);
    dim3 grid(NN / BN, NN / BM);
    gemm_argmin<<<grid, 256>>>(X);
    gather_kernel<<<dim3(NN, 2), 256>>>(X, out);
}

// round 4
// speedup vs baseline: 2.8990x; 2.8990x over previous
#include <cuda_runtime.h>
#include <cstdint>

#define NN 4096
#define DD 1024
#define BM 128
#define BN 128
#define BK 16

// Per-row argmin keys: (orderable(value) << 32) | col_index. min key == argmin
// with first-index tie-break, identical to jnp.argmin semantics.
__device__ unsigned long long g_ap[NN];
__device__ unsigned long long g_an[NN];
__device__ int g_lab[NN];
__device__ int g_is64;

// ---------------------------------------------------------------------------
// Detect int64-vs-int32 labels (JAX demotes int64 -> int32 without x64).
// ---------------------------------------------------------------------------
__global__ void detect_kernel(const int* __restrict__ lab32) {
    __shared__ int any;
    if (threadIdx.x == 0) any = 0;
    __syncthreads();
    int acc = 0;
    for (int i = 1 + 2 * threadIdx.x; i < 4096; i += 2 * blockDim.x)
        acc |= lab32[i];
    if (acc) atomicOr(&any, 1);
    __syncthreads();
    if (threadIdx.x == 0) g_is64 = (any == 0) ? 1 : 0;
}

__global__ void init_kernel(const int* __restrict__ lab32) {
    int i = blockIdx.x * blockDim.x + threadIdx.x;
    if (i < NN) {
        g_ap[i] = 0xFFFFFFFFFFFFFFFFull;
        g_an[i] = 0xFFFFFFFFFFFFFFFFull;
        g_lab[i] = g_is64 ? lab32[2 * i] : lab32[i];
    }
}

__device__ __forceinline__ unsigned float_order(float f) {
    unsigned u = __float_as_uint(f);
    return (u & 0x80000000u) ? ~u : (u | 0x80000000u);
}

// ---------------------------------------------------------------------------
// Symmetric fused SGEMM + masked argmin.
// Only lower-triangular tiles (bi >= bj) are computed; each off-diagonal tile
// updates row-argmins (rows of tile bi vs cols of tile bj) AND column-argmins
// (rows of tile bj vs cols of tile bi) since values and masks are symmetric.
// 128x128 tile, 256 threads, 8x8 micro-tile, double-buffered smem.
// ---------------------------------------------------------------------------
__global__ __launch_bounds__(256, 2)
void gemm_argmin_sym(const float* __restrict__ X) {
    __shared__ float As[2][BK][BM + 4];
    __shared__ float Bs[2][BK][BN + 4];
    __shared__ int labA[BM];
    __shared__ int labB[BN];
    __shared__ unsigned long long colAp[BN];
    __shared__ unsigned long long colAn[BN];

    const int t  = threadIdx.x;
    const int tx = t & 15;
    const int ty = t >> 4;

    // ---- triangular decode: tile -> (bi, bj), bi >= bj --------------------
    const int tile = blockIdx.x;
    int bi = (int)((sqrtf(8.0f * (float)tile + 1.0f) - 1.0f) * 0.5f);
    while ((bi + 1) * (bi + 2) / 2 <= tile) bi++;
    while (bi * (bi + 1) / 2 > tile) bi--;
    const int bj = tile - bi * (bi + 1) / 2;
    const bool diag = (bi == bj);

    const int rowBase = bi * BM;
    const int colBase = bj * BN;

    if (t < BM)      labA[t]      = g_lab[rowBase + t];
    else             labB[t - BM] = g_lab[colBase + (t - BM)];
    if (t < BN) { colAp[t] = 0xFFFFFFFFFFFFFFFFull; colAn[t] = 0xFFFFFFFFFFFFFFFFull; }

    float acc[8][8];
#pragma unroll
    for (int i = 0; i < 8; i++)
#pragma unroll
        for (int j = 0; j < 8; j++) acc[i][j] = 0.0f;

    const float* Arow = X + (size_t)rowBase * DD;
    const float* Brow = X + (size_t)colBase * DD;

    const int lr  = t >> 2;   // 0..63
    const int lc4 = t & 3;    // 0..3

    float4 pa0, pa1, pb0, pb1;

    // prologue: load k0 = 0
    pa0 = *(const float4*)(Arow + (size_t)lr        * DD + lc4 * 4);
    pa1 = *(const float4*)(Arow + (size_t)(lr + 64) * DD + lc4 * 4);
    pb0 = *(const float4*)(Brow + (size_t)lr        * DD + lc4 * 4);
    pb1 = *(const float4*)(Brow + (size_t)(lr + 64) * DD + lc4 * 4);

    {
        const int c = lc4 * 4;
        As[0][c + 0][lr] = pa0.x; As[0][c + 1][lr] = pa0.y;
        As[0][c + 2][lr] = pa0.z; As[0][c + 3][lr] = pa0.w;
        As[0][c + 0][lr + 64] = pa1.x; As[0][c + 1][lr + 64] = pa1.y;
        As[0][c + 2][lr + 64] = pa1.z; As[0][c + 3][lr + 64] = pa1.w;
        Bs[0][c + 0][lr] = pb0.x; Bs[0][c + 1][lr] = pb0.y;
        Bs[0][c + 2][lr] = pb0.z; Bs[0][c + 3][lr] = pb0.w;
        Bs[0][c + 0][lr + 64] = pb1.x; Bs[0][c + 1][lr + 64] = pb1.y;
        Bs[0][c + 2][lr + 64] = pb1.z; Bs[0][c + 3][lr + 64] = pb1.w;
    }
    __syncthreads();

    int buf = 0;
    for (int k0 = BK; k0 < DD; k0 += BK) {
        // issue next-tile global loads early (latency hidden under FFMAs)
        pa0 = *(const float4*)(Arow + (size_t)lr        * DD + k0 + lc4 * 4);
        pa1 = *(const float4*)(Arow + (size_t)(lr + 64) * DD + k0 + lc4 * 4);
        pb0 = *(const float4*)(Brow + (size_t)lr        * DD + k0 + lc4 * 4);
        pb1 = *(const float4*)(Brow + (size_t)(lr + 64) * DD + k0 + lc4 * 4);

#pragma unroll
        for (int kk = 0; kk < BK; kk++) {
            float4 a0 = *(const float4*)&As[buf][kk][ty * 8];
            float4 a1 = *(const float4*)&As[buf][kk][ty * 8 + 4];
            float4 b0 = *(const float4*)&Bs[buf][kk][tx * 8];
            float4 b1 = *(const float4*)&Bs[buf][kk][tx * 8 + 4];
            float a[8] = {a0.x, a0.y, a0.z, a0.w, a1.x, a1.y, a1.z, a1.w};
            float b[8] = {b0.x, b0.y, b0.z, b0.w, b1.x, b1.y, b1.z, b1.w};
#pragma unroll
            for (int i = 0; i < 8; i++)
#pragma unroll
                for (int j = 0; j < 8; j++)
                    acc[i][j] += a[i] * b[j];
        }

        const int nb = buf ^ 1;
        const int c = lc4 * 4;
        As[nb][c + 0][lr] = pa0.x; As[nb][c + 1][lr] = pa0.y;
        As[nb][c + 2][lr] = pa0.z; As[nb][c + 3][lr] = pa0.w;
        As[nb][c + 0][lr + 64] = pa1.x; As[nb][c + 1][lr + 64] = pa1.y;
        As[nb][c + 2][lr + 64] = pa1.z; As[nb][c + 3][lr + 64] = pa1.w;
        Bs[nb][c + 0][lr] = pb0.x; Bs[nb][c + 1][lr] = pb0.y;
        Bs[nb][c + 2][lr] = pb0.z; Bs[nb][c + 3][lr] = pb0.w;
        Bs[nb][c + 0][lr + 64] = pb1.x; Bs[nb][c + 1][lr + 64] = pb1.y;
        Bs[nb][c + 2][lr + 64] = pb1.z; Bs[nb][c + 3][lr + 64] = pb1.w;
        __syncthreads();
        buf = nb;
    }

#pragma unroll
    for (int kk = 0; kk < BK; kk++) {
        float4 a0 = *(const float4*)&As[buf][kk][ty * 8];
        float4 a1 = *(const float4*)&As[buf][kk][ty * 8 + 4];
        float4 b0 = *(const float4*)&Bs[buf][kk][tx * 8];
        float4 b1 = *(const float4*)&Bs[buf][kk][tx * 8 + 4];
        float a[8] = {a0.x, a0.y, a0.z, a0.w, a1.x, a1.y, a1.z, a1.w};
        float b[8] = {b0.x, b0.y, b0.z, b0.w, b1.x, b1.y, b1.z, b1.w};
#pragma unroll
        for (int i = 0; i < 8; i++)
#pragma unroll
            for (int j = 0; j < 8; j++)
                acc[i][j] += a[i] * b[j];
    }

    // ---- row epilogue: rows of tile bi, candidate cols of tile bj ---------
#pragma unroll
    for (int i = 0; i < 8; i++) {
        const int r   = rowBase + ty * 8 + i;
        const int lri = labA[ty * 8 + i];
        unsigned long long kap = 0xFFFFFFFFFFFFFFFFull;
        unsigned long long kan = 0xFFFFFFFFFFFFFFFFull;
#pragma unroll
        for (int j = 0; j < 8; j++) {
            const int c    = colBase + tx * 8 + j;
            const bool same = (lri == labB[tx * 8 + j]);
            const float v  = acc[i][j];
            const float vap = v + ((same && (r != c)) ? 0.0f : 2.0f);
            const float van = v + (same ? 2.0f : 0.0f);
            unsigned long long k1 =
                ((unsigned long long)float_order(vap) << 32) | (unsigned)c;
            unsigned long long k2 =
                ((unsigned long long)float_order(van) << 32) | (unsigned)c;
            kap = (k1 < kap) ? k1 : kap;
            kan = (k2 < kan) ? k2 : kan;
        }
#pragma unroll
        for (int off = 8; off >= 1; off >>= 1) {
            unsigned long long o1 = __shfl_xor_sync(0xffffffffu, kap, off);
            unsigned long long o2 = __shfl_xor_sync(0xffffffffu, kan, off);
            kap = (o1 < kap) ? o1 : kap;
            kan = (o2 < kan) ? o2 : kan;
        }
        if (tx == 0) {
            atomicMin(&g_ap[r], kap);
            atomicMin(&g_an[r], kan);
        }
    }

    // ---- column epilogue (off-diagonal only): rows of tile bj get
    //      candidates from tile bi via symmetry (r != c guaranteed) ---------
    if (!diag) {
        __syncthreads();  // colAp/colAn init visible (done at kernel start)
#pragma unroll
        for (int j = 0; j < 8; j++) {
            const int lcj = labB[tx * 8 + j];
            unsigned long long kap = 0xFFFFFFFFFFFFFFFFull;
            unsigned long long kan = 0xFFFFFFFFFFFFFFFFull;
#pragma unroll
            for (int i = 0; i < 8; i++) {
                const int r    = rowBase + ty * 8 + i;  // candidate index
                const bool same = (labA[ty * 8 + i] == lcj);
                const float v  = acc[i][j];
                const float vap = v + (same ? 0.0f : 2.0f);
                const float van = v + (same ? 2.0f : 0.0f);
                unsigned long long k1 =
                    ((unsigned long long)float_order(vap) << 32) | (unsigned)r;
                unsigned long long k2 =
                    ((unsigned long long)float_order(van) << 32) | (unsigned)r;
                kap = (k1 < kap) ? k1 : kap;
                kan = (k2 < kan) ? k2 : kan;
            }
            atomicMin(&colAp[tx * 8 + j], kap);
            atomicMin(&colAn[tx * 8 + j], kan);
        }
        __syncthreads();
        if (t < BN) {
            atomicMin(&g_ap[colBase + t], colAp[t]);
            atomicMin(&g_an[colBase + t], colAn[t]);
        }
    }
}

// ---------------------------------------------------------------------------
// Gather: out[0][r][:] = X[id_ap[r]], out[1][r][:] = X[id_an[r]]
// ---------------------------------------------------------------------------
__global__ void gather_kernel(const float* __restrict__ X, float* __restrict__ out) {
    const int r     = blockIdx.x;
    const int which = blockIdx.y;
    const unsigned idx =
        (unsigned)((which ? g_an[r] : g_ap[r]) & 0xFFFFFFFFull);
    const float4* src = (const float4*)(X + (size_t)idx * DD);
    float4* dst = (float4*)(out + ((size_t)which * NN + r) * DD);
    for (int i = threadIdx.x; i < DD / 4; i += blockDim.x)
        dst[i] = src[i];
}

extern "C" void kernel_launch(void* const* d_in, const int* in_sizes, int n_in,
                              void* d_out, int out_size) {
    const float* X   = (const float*)d_in[0];
    const int*   lab = (const int*)d_in[1];
    float*       out = (float*)d_out;

    detect_kernel<<<1, 256>>>(lab);
    init_kernel<<<16, 256>>>(lab);
    const int ntiles = (NN / BM) * (NN / BM + 1) / 2;  // 32*33/2 = 528
    gemm_argmin_sym<<<ntiles, 256>>>(X);
    gather_kernel<<<dim3(NN, 2), 256>>>(X, out);
}